// round 17
// baseline (speedup 1.0000x reference)
#include <cuda_runtime.h>
#include <cuda_fp16.h>
#include <cstdint>
#include <math.h>

#define HID    768
#define FFNDIM 3072
#define NE     8
#define TMAX   16384

// ---------------- scratch (device globals: allocation-free) ----------------
__device__ __half g_xh [TMAX * HID];            // fp16 X
__device__ __half g_w1h[NE * FFNDIM * HID];     // w1 transposed: [E][FFN][HID] fp16
__device__ __half g_w2h[NE * HID * FFNDIM];     // w2 transposed: [E][HID][FFN] fp16
__device__ __half g_Hh [2 * TMAX * FFNDIM];     // gelu(X@w1+b1) fp16
__device__ int    g_cnt[NE];
__device__ int    g_list[NE * TMAX];            // expert,slot -> token
__device__ float  g_gslot[NE * TMAX];           // expert,slot -> gate
__device__ float  g_probsum[NE];
__device__ float  g_gatesum[NE];

// ---------------- helpers ----------------
__device__ __forceinline__ void cp16(uint32_t dst, const void* src) {
    asm volatile("cp.async.cg.shared.global [%0], [%1], 16;" :: "r"(dst), "l"(src));
}
__device__ __forceinline__ float fast_tanh(float y) {
    float t = __expf(2.0f * fminf(fabsf(y), 15.0f));
    float r = (t - 1.0f) / (t + 1.0f);
    return copysignf(r, y);
}
__device__ __forceinline__ float gelu_tanh(float x) {
    float x3 = x * x * x;
    return 0.5f * x * (1.0f + fast_tanh(0.7978845608028654f * (x + 0.044715f * x3)));
}

#define LDSM4(r0, r1, r2, r3, addr) \
    asm volatile("ldmatrix.sync.aligned.m8n8.x4.shared.b16 {%0,%1,%2,%3}, [%4];" \
                 : "=r"(r0), "=r"(r1), "=r"(r2), "=r"(r3) : "r"(addr))

#define MMA16816(acc, a, b) \
    asm volatile( \
        "mma.sync.aligned.m16n8k16.row.col.f32.f16.f16.f32 " \
        "{%0,%1,%2,%3}, {%4,%5,%6,%7}, {%8,%9}, {%0,%1,%2,%3};\n" \
        : "+f"((acc)[0]), "+f"((acc)[1]), "+f"((acc)[2]), "+f"((acc)[3]) \
        : "r"((a)[0]), "r"((a)[1]), "r"((a)[2]), "r"((a)[3]), \
          "r"((b)[0]), "r"((b)[1]))

// ---------------- init (orders before the front kernel's router atomics) ----
__global__ void init_kernel() {
    int i = threadIdx.x;
    if (i < NE) { g_cnt[i] = 0; g_probsum[i] = 0.f; g_gatesum[i] = 0.f; }
}

// ---------------- front: router (z=0, dispatched FIRST) + w1 transpose ------
// grid (96, 24, 9), block (32, 8).
//   z == 0     : router (fused x->fp16 convert; records g_list/g_gslot)
//   z in [1,9) : transpose w1 expert z-1 (w2 is handled inside gemm1's helpers)
__global__ void __launch_bounds__(256) front_kernel(
    const float* __restrict__ x,  const float* __restrict__ w1,
    const float* __restrict__ rw, const float* __restrict__ rb,
    float* __restrict__ out_rw, float* __restrict__ out_mask,
    float* __restrict__ out_logits, int T)
{
    __shared__ float tile[32][33];
    __shared__ float srw[NE * HID];
    __shared__ float sprob[NE];
    __shared__ float sgate[NE];

    const int tx = threadIdx.x, ty = threadIdx.y;
    const int tid = ty * 32 + tx;
    const int z = blockIdx.z;

    if (z > 0) {
        // ---- w1 transpose: src [HID][FFN] -> dst [FFN][HID] ----
        const int e = z - 1;
        const float* s = w1 + (size_t)e * HID * FFNDIM;
        __half* d = g_w1h + (size_t)e * HID * FFNDIM;
        int c0 = blockIdx.x * 32, r0 = blockIdx.y * 32;
        #pragma unroll
        for (int i = 0; i < 32; i += 8)
            tile[ty + i][tx] = s[(size_t)(r0 + ty + i) * FFNDIM + c0 + tx];
        __syncthreads();
        #pragma unroll
        for (int i = 0; i < 32; i += 8)
            d[(size_t)(c0 + ty + i) * HID + r0 + tx] = __float2half_rn(tile[tx][ty + i]);
        return;
    }

    // ---- z == 0: router (+ fused fp16 convert of x) ----
    for (int i = tid; i < NE * HID; i += 256) {
        int e = i / HID, c = i - e * HID;
        srw[i] = rw[c * NE + e];
    }
    if (tid < NE) { sprob[tid] = 0.f; sgate[tid] = 0.f; }
    __syncthreads();

    const int warp = ty, lane = tx;
    const int bid = blockIdx.y * gridDim.x + blockIdx.x;
    const int t = bid * 8 + warp;
    if (t < T) {
        float p[NE];
        #pragma unroll
        for (int e = 0; e < NE; e++) p[e] = 0.f;
        const float* xr = x + (size_t)t * HID;
        __half* xhr = g_xh + (size_t)t * HID;
        for (int c = lane; c < HID; c += 32) {
            float xv = xr[c];
            xhr[c] = __float2half_rn(xv);
            #pragma unroll
            for (int e = 0; e < NE; e++) p[e] += xv * srw[e * HID + c];
        }
        #pragma unroll
        for (int e = 0; e < NE; e++) {
            #pragma unroll
            for (int o = 16; o > 0; o >>= 1)
                p[e] += __shfl_xor_sync(0xffffffffu, p[e], o);
        }
        if (lane == 0) {
            float lg[NE];
            #pragma unroll
            for (int e = 0; e < NE; e++) lg[e] = p[e] + rb[e];
            float m = lg[0];
            #pragma unroll
            for (int e = 1; e < NE; e++) m = fmaxf(m, lg[e]);
            float s = 0.f, pr[NE];
            #pragma unroll
            for (int e = 0; e < NE; e++) { pr[e] = expf(lg[e] - m); s += pr[e]; }
            float inv = 1.f / s;
            #pragma unroll
            for (int e = 0; e < NE; e++) {
                pr[e] *= inv;
                out_logits[(size_t)t * NE + e] = lg[e];
                out_rw[(size_t)t * NE + e] = pr[e];
                atomicAdd(&sprob[e], pr[e]);
            }
            int i1 = 0; float v1 = lg[0];
            #pragma unroll
            for (int e = 1; e < NE; e++) if (lg[e] > v1) { v1 = lg[e]; i1 = e; }
            int i2 = -1; float v2 = -3.4e38f;
            #pragma unroll
            for (int e = 0; e < NE; e++)
                if (e != i1 && lg[e] > v2) { v2 = lg[e]; i2 = e; }
            float texp = expf(v2 - v1);
            float gden = 1.f / (1.f + texp);
            float gg1 = gden, gg2 = texp * gden;
            #pragma unroll
            for (int e = 0; e < NE; e++) {
                float mv = (e == i1) ? gg1 : ((e == i2) ? gg2 : 0.f);
                out_mask[(size_t)t * NE + e] = mv;
            }
            int pos1 = atomicAdd(&g_cnt[i1], 1);
            g_list[i1 * TMAX + pos1] = t;
            g_gslot[i1 * TMAX + pos1] = gg1;
            int pos2 = atomicAdd(&g_cnt[i2], 1);
            g_list[i2 * TMAX + pos2] = t;
            g_gslot[i2 * TMAX + pos2] = gg2;
            atomicAdd(&sgate[i1], gg1);
            atomicAdd(&sgate[i2], gg2);
        }
    }
    __syncthreads();
    if (tid < NE) {
        atomicAdd(&g_probsum[tid], sprob[tid]);
        atomicAdd(&g_gatesum[tid], sgate[tid]);
    }
}

// ---------------- fp16 mma.sync grouped GEMM (round-8 winner core) ----------
// CTA tile 256(M) x 128(N) x 64(K), 512 threads = 16 warps (4x4), warp tile 64x32.
// 4-stage cp.async ring, prefetch dist 2, single sync per k-tile, ldmatrix.x4.
// EPI=1: out = fp16(gelu(.+b1)) -> g_Hh. grid.x = FFNDIM/BN + 1: blocks with
//   x == gridDim.x-1 are INTERLEAVED HELPERS (every 25th dispatch slot) that
//   transpose w2 + zero d_out + compute aux_loss under gemm1's idle DRAM.
// EPI=2: FUSED COMBINE: atomicAdd(out[tok], gate * (.+b2)).
// g_off is gone: every CTA computes its own 8-entry prefix sum from g_cnt.
#define BM      256
#define BN      128
#define BK      64
#define ROWH    72                    // padded row length in halves (144 B)
#define ROWB    144
#define TILEA_B (BM * ROWB)           // 36864 B
#define TILEB_B (BN * ROWB)           // 18432 B
#define STAGEB  (TILEA_B + TILEB_B)   // 55296 B
#define NSTAGE  4
#define W2TILES (NE * (FFNDIM / 32) * (HID / 32))   // 18432

template<int KDIM, int NDIM, int EPI>
__global__ void __launch_bounds__(512, 1) gemmh_kernel(
    const float* __restrict__ bias, float* __restrict__ outp,
    const float* __restrict__ w2src, float* __restrict__ out_aux, int T)
{
    extern __shared__ __half smem[];

    if (EPI == 1 && blockIdx.x == gridDim.x - 1) {
        // ---- interleaved helper: w2 transpose + zero d_out + aux ----
        const int nh = gridDim.y * gridDim.z;
        const int h  = blockIdx.z * gridDim.y + blockIdx.y;
        const int tid = threadIdx.x;
        float (*tile2)[32][33] = reinterpret_cast<float (*)[32][33]>(smem);
        const int sub = tid >> 8;             // 0..1
        const int t8  = tid & 255;
        const int tx  = t8 & 31, ty = t8 >> 5;

        if (h == 0 && tid == 0) {
            float aux = 0.f;
            #pragma unroll
            for (int e = 0; e < NE; e++) aux += g_probsum[e] * g_gatesum[e];
            out_aux[0] = aux * (float)NE / ((float)T * (float)T);
        }
        // zero combined output stripe (float4)
        {
            int total4 = T * (HID / 4);
            float4 zv = make_float4(0.f, 0.f, 0.f, 0.f);
            for (int i = h * 512 + tid; i < total4; i += nh * 512)
                reinterpret_cast<float4*>(outp)[i] = zv;
        }
        // w2 transpose: tiles h*2+sub, stepping nh*2
        const int per = 2 * ((W2TILES / 2 + nh - 1) / nh);
        for (int k = 0; k < per / 2; k++) {
            int tileid = (h + k * nh) * 2 + sub;
            if (tileid < W2TILES) {
                int e  = tileid / ((FFNDIM / 32) * (HID / 32));
                int rm = tileid - e * ((FFNDIM / 32) * (HID / 32));
                int fb = rm / (HID / 32);
                int hb = rm - fb * (HID / 32);
                const float* s = w2src + (size_t)e * FFNDIM * HID;
                __half* d = g_w2h + (size_t)e * FFNDIM * HID;
                int r0 = fb * 32, c0 = hb * 32;
                #pragma unroll
                for (int i = 0; i < 32; i += 8)
                    tile2[sub][ty + i][tx] = s[(size_t)(r0 + ty + i) * HID + c0 + tx];
                __syncthreads();
                #pragma unroll
                for (int i = 0; i < 32; i += 8)
                    d[(size_t)(c0 + ty + i) * FFNDIM + r0 + tx] =
                        __float2half_rn(tile2[sub][tx][ty + i]);
                __syncthreads();
            }
        }
        return;
    }

    const int e   = blockIdx.z;
    const int cnt = g_cnt[e];
    const int m0  = blockIdx.y * BM;
    if (m0 >= cnt) return;
    const int n0  = blockIdx.x * BN;
    int off = 0;
    for (int i = 0; i < e; i++) off += g_cnt[i];

    const uint32_t SB = (uint32_t)__cvta_generic_to_shared(smem);

    const int tid  = threadIdx.x;
    const int lane = tid & 31;
    const int wid  = tid >> 5;
    const int wm   = wid >> 2;          // 0..3
    const int wn   = wid & 3;           // 0..3
    const int gid  = lane >> 2;         // 0..7
    const int tig  = lane & 3;          // 0..3

    // ---- cp.async plumbing: 4 A rows + 2 B rows per thread ----
    const int chunk = tid & 7;          // 0..7  (16B = 8 halves)
    const int row4  = tid >> 3;         // 0..63
    const __half* asrc[4];
    const __half* bsrc[2];
    uint32_t adst[4], bdst[2];
    const __half* wT = (EPI == 1 ? g_w1h : g_w2h) + (size_t)e * KDIM * NDIM;
    #pragma unroll
    for (int i = 0; i < 4; i++) {
        int row = row4 + 64 * i;        // 0..255
        int slot = m0 + row;
        if (slot > cnt - 1) slot = cnt - 1;
        if (EPI == 1) {
            int tok = g_list[e * TMAX + slot];
            asrc[i] = g_xh + (size_t)tok * KDIM + chunk * 8;
        } else {
            asrc[i] = g_Hh + (size_t)(off + slot) * KDIM + chunk * 8;
        }
        adst[i] = SB + (uint32_t)(row * ROWB + chunk * 16);
    }
    #pragma unroll
    for (int i = 0; i < 2; i++) {
        int row = row4 + 64 * i;        // 0..127
        bsrc[i] = wT + (size_t)(n0 + row) * KDIM + chunk * 8;
        bdst[i] = SB + TILEA_B + (uint32_t)(row * ROWB + chunk * 16);
    }

    auto load_stage = [&](int s, int k0) {
        uint32_t so = (uint32_t)s * STAGEB;
        #pragma unroll
        for (int i = 0; i < 4; i++) cp16(adst[i] + so, asrc[i] + k0);
        #pragma unroll
        for (int i = 0; i < 2; i++) cp16(bdst[i] + so, bsrc[i] + k0);
    };

    float acc[4][4][4];
    #pragma unroll
    for (int mi = 0; mi < 4; mi++)
        #pragma unroll
        for (int ni = 0; ni < 4; ni++)
            #pragma unroll
            for (int r = 0; r < 4; r++) acc[mi][ni][r] = 0.f;

    constexpr int NKT = KDIM / BK;
    load_stage(0, 0);
    asm volatile("cp.async.commit_group;" ::: "memory");
    load_stage(1, BK);
    asm volatile("cp.async.commit_group;" ::: "memory");

    const int mbase = wm * 64;
    const int nbase = wn * 32;

    // ---- per-lane ldmatrix byte offsets (round-8 verified maps) ----
    const int lgrp = lane >> 3, lr = lane & 7;
    const uint32_t a_lane = (uint32_t)((((lgrp & 1) * 8 + lr) * ROWH + (lgrp >> 1) * 8) * 2);
    const uint32_t b_lane = (uint32_t)((((lgrp >> 1) * 8 + lr) * ROWH + (lgrp & 1) * 8) * 2);

    for (int kt = 0; kt < NKT; kt++) {
        if (kt + 2 < NKT) load_stage((kt + 2) & 3, (kt + 2) * BK);
        asm volatile("cp.async.commit_group;" ::: "memory");
        asm volatile("cp.async.wait_group 2;" ::: "memory");
        __syncthreads();

        const uint32_t stage = SB + (uint32_t)(kt & 3) * STAGEB;
        const uint32_t asb = stage + (uint32_t)(mbase * ROWB) + a_lane;
        const uint32_t bsb = stage + TILEA_B + (uint32_t)(nbase * ROWB) + b_lane;
        #pragma unroll
        for (int kk = 0; kk < BK; kk += 16) {
            uint32_t a[4][4], b[4][2];
            #pragma unroll
            for (int mi = 0; mi < 4; mi++)
                LDSM4(a[mi][0], a[mi][1], a[mi][2], a[mi][3],
                      asb + (uint32_t)(mi * 16 * ROWB + kk * 2));
            #pragma unroll
            for (int p = 0; p < 2; p++)
                LDSM4(b[2 * p][0], b[2 * p][1], b[2 * p + 1][0], b[2 * p + 1][1],
                      bsb + (uint32_t)(p * 16 * ROWB + kk * 2));
            #pragma unroll
            for (int mi = 0; mi < 4; mi++)
                #pragma unroll
                for (int ni = 0; ni < 4; ni++)
                    MMA16816(acc[mi][ni], a[mi], b[ni]);
        }
    }

    // ---- epilogue ----
    int   toks [4][2];
    float gates[4][2];
    if (EPI == 2) {
        #pragma unroll
        for (int mi = 0; mi < 4; mi++) {
            int r = m0 + wm * 64 + mi * 16 + gid;
            #pragma unroll
            for (int h = 0; h < 2; h++) {
                int rr = r + h * 8;
                if (rr < cnt) {
                    toks [mi][h] = g_list [e * TMAX + rr];
                    gates[mi][h] = g_gslot[e * TMAX + rr];
                } else { toks[mi][h] = 0; gates[mi][h] = 0.f; }
            }
        }
    }
    #pragma unroll
    for (int ni = 0; ni < 4; ni++) {
        int cc = n0 + wn * 32 + ni * 8 + 2 * tig;
        float bv0 = bias[e * NDIM + cc];
        float bv1 = bias[e * NDIM + cc + 1];
        #pragma unroll
        for (int mi = 0; mi < 4; mi++) {
            int r = m0 + wm * 64 + mi * 16 + gid;
            #pragma unroll
            for (int h = 0; h < 2; h++) {
                int rr = r + h * 8;
                if (rr < cnt) {
                    float v0 = acc[mi][ni][2 * h]     + bv0;
                    float v1 = acc[mi][ni][2 * h + 1] + bv1;
                    if (EPI == 1) {
                        __half2 hv = __floats2half2_rn(gelu_tanh(v0), gelu_tanh(v1));
                        *reinterpret_cast<__half2*>(
                            &g_Hh[(size_t)(off + rr) * NDIM + cc]) = hv;
                    } else {
                        float g = gates[mi][h];
                        float* orow = outp + (size_t)toks[mi][h] * NDIM + cc;
                        atomicAdd(orow,     g * v0);
                        atomicAdd(orow + 1, g * v1);
                    }
                }
            }
        }
    }
}

// ---------------- launch ----------------
extern "C" void kernel_launch(void* const* d_in, const int* in_sizes, int n_in,
                              void* d_out, int out_size)
{
    const float* x  = (const float*)d_in[0];
    const float* rw = (const float*)d_in[1];
    const float* rb = (const float*)d_in[2];
    const float* w1 = (const float*)d_in[3];
    const float* b1 = (const float*)d_in[4];
    const float* w2 = (const float*)d_in[5];
    const float* b2 = (const float*)d_in[6];
    int T = in_sizes[0] / HID;
    if (T > TMAX) T = TMAX;

    float* out        = (float*)d_out;
    float* out_comb   = out;
    float* out_rw     = out + (size_t)T * HID;
    float* out_mask   = out_rw + (size_t)T * NE;
    float* out_aux    = out_mask + (size_t)T * NE;
    float* out_logits = out_aux + 1;

    const int smem = NSTAGE * STAGEB;   // 221184 B
    cudaFuncSetAttribute(gemmh_kernel<HID, FFNDIM, 1>,
                         cudaFuncAttributeMaxDynamicSharedMemorySize, smem);
    cudaFuncSetAttribute(gemmh_kernel<FFNDIM, HID, 2>,
                         cudaFuncAttributeMaxDynamicSharedMemorySize, smem);

    init_kernel<<<1, 32>>>();
    front_kernel<<<dim3(96, 24, 9), dim3(32, 8)>>>(
        x, w1, rw, rb, out_rw, out_mask, out_logits, T);

    int mt = (T + BM - 1) / BM;
    gemmh_kernel<HID, FFNDIM, 1><<<dim3(FFNDIM / BN + 1, mt, NE), 512, smem>>>(
        b1, out_comb, w2, out_aux, T);
    gemmh_kernel<FFNDIM, HID, 2><<<dim3(HID / BN, mt, NE), 512, smem>>>(
        b2, out_comb, nullptr, out_aux, T);
}